// round 4
// baseline (speedup 1.0000x reference)
#include <cuda_runtime.h>
#include <cstdint>
#include <math.h>

// Problem constants
constexpr int NN    = 4096;          // number of vertices / matrix dim
constexpr int TPB   = 512;           // threads per MST block
constexpr int SLICE = NN / TPB;      // 8 vertices per thread
constexpr int NWARP = TPB / 32;      // 16 warps

// Scratch (no allocations allowed): final Prim parent arrays for both matrices.
__device__ int g_parent[2][NN];

__device__ __forceinline__ unsigned long long u64min(unsigned long long a, unsigned long long b) {
    return b < a ? b : a;
}

// ---------------------------------------------------------------------------
// Exact Prim's MST, one persistent CTA per matrix (gridDim.x == 2).
//
// State layout: thread t owns vertices [8t, 8t+8).
//   md[k]  : current best edge weight from the tree to vertex 8t+k.
//            Sign bit set  <=>  vertex is in the tree ("in_tree" folded into md):
//            - strict relaxation rv < md is always false vs a negative md
//              (rv >= 0 for distances)
//            - packed argmin key (bits<<32 | idx) sorts negatives after ALL
//              nonnegative floats (incl. +inf), so in-tree vertices never win.
//   par[k] : tree endpoint realizing md (frozen once the vertex is popped).
//
// Tie-break matches jnp.argmin (first index): key = (float_bits<<32)|idx,
// u64-min over all candidates.
// ---------------------------------------------------------------------------
__global__ __launch_bounds__(TPB, 1)
void mst_kernel(const float* __restrict__ d1, const float* __restrict__ d2) {
    const float* __restrict__ D = blockIdx.x ? d2 : d1;
    const int t    = threadIdx.x;
    const int wid  = t >> 5;
    const int lane = t & 31;

    __shared__ unsigned long long partials[2][NWARP];   // double-buffered per iteration

    float md[SLICE];
    int   par[SLICE];

    // ---- init: min_dist = D[0, :], parent = 0, vertex 0 in tree ----
    {
        const float4* row = reinterpret_cast<const float4*>(D) + t * (SLICE / 4);
        float4 a = row[0];
        float4 b = row[1];
        md[0] = a.x; md[1] = a.y; md[2] = a.z; md[3] = a.w;
        md[4] = b.x; md[5] = b.y; md[6] = b.z; md[7] = b.w;
    }
#pragma unroll
    for (int k = 0; k < SLICE; ++k) par[k] = 0;
    if (t == 0) md[0] = __uint_as_float(0xFF800000u);   // vertex 0: -inf => in tree

    // local argmin key over owned slice
    unsigned long long key = ~0ull;
#pragma unroll
    for (int k = 0; k < SLICE; ++k) {
        unsigned long long kk =
            ((unsigned long long)__float_as_uint(md[k]) << 32) | (unsigned)(t * SLICE + k);
        key = u64min(key, kk);
    }

    for (int sel = 0; sel < NN - 1; ++sel) {
        // warp-level u64 min (full 32-lane butterfly)
#pragma unroll
        for (int o = 16; o; o >>= 1)
            key = u64min(key, __shfl_xor_sync(0xFFFFFFFFu, key, o));
        if (lane == 0) partials[sel & 1][wid] = key;
        __syncthreads();

        // Every warp redundantly combines the 16 partials -> j known to all
        // lanes with no second barrier. NOTE: lanes 16..31 must mirror lanes
        // 0..15 (lane & 15) because the 8/4/2/1 butterfly keeps the two
        // half-warps disjoint — loading ~0ull there was the R2 bug.
        unsigned long long k2 = partials[sel & 1][lane & (NWARP - 1)];
#pragma unroll
        for (int o = 8; o; o >>= 1)
            k2 = u64min(k2, __shfl_xor_sync(0xFFFFFFFFu, k2, o));
        const int j = (int)(unsigned)(k2 & 0xFFFFFFFFu);

        // owner marks j as in-tree (sign-bit flip), static register indexing only
        if ((j >> 3) == t) {
#pragma unroll
            for (int k = 0; k < SLICE; ++k)
                if (k == (j & (SLICE - 1)))
                    md[k] = __uint_as_float(__float_as_uint(md[k]) | 0x80000000u);
        }
        if (sel == NN - 2) break;   // last vertex popped, no relaxation needed

        // relax with row j (fused with local argmin recompute)
        const float4* row = reinterpret_cast<const float4*>(D + (size_t)j * NN) + t * (SLICE / 4);
        float4 a = row[0];
        float4 b = row[1];
        float rv[SLICE] = {a.x, a.y, a.z, a.w, b.x, b.y, b.z, b.w};
        key = ~0ull;
#pragma unroll
        for (int k = 0; k < SLICE; ++k) {
            if (rv[k] < md[k]) { md[k] = rv[k]; par[k] = j; }   // strict <, matches reference
            unsigned long long kk =
                ((unsigned long long)__float_as_uint(md[k]) << 32) | (unsigned)(t * SLICE + k);
            key = u64min(key, kk);
        }
    }

    // parents are frozen at pop time; write once at the end
#pragma unroll
    for (int k = 0; k < SLICE; ++k)
        g_parent[blockIdx.x][t * SLICE + k] = par[k];
}

// ---------------------------------------------------------------------------
// Gather signatures, fp64 sums, sqrt, matched-pair count.
// Each child c in 1..N-1 appears exactly once in each pair list, so
// matched_pairs = #{ c : parent1[c] == parent2[c] }.
// ---------------------------------------------------------------------------
__global__ void finalize_kernel(const float* __restrict__ d1, const float* __restrict__ d2,
                                float* __restrict__ out, int out_size) {
    constexpr int FT = 256;
    __shared__ double s12[FT];
    __shared__ double s21[FT];
    __shared__ int    sm[FT];
    const int t = threadIdx.x;

    double a12 = 0.0, a21 = 0.0;
    int m = 0;
    for (int c = 1 + t; c < NN; c += FT) {
        int p1 = g_parent[0][c];
        int p2 = g_parent[1][c];
        float x1 = d1[(size_t)p1 * NN + c];   // sig1
        float y1 = d2[(size_t)p1 * NN + c];   // sig1_2
        float x2 = d2[(size_t)p2 * NN + c];   // sig2
        float y2 = d1[(size_t)p2 * NN + c];   // sig2_1
        double e1 = (double)x1 - (double)y1;
        double e2 = (double)x2 - (double)y2;
        a12 += e1 * e1;
        a21 += e2 * e2;
        m += (p1 == p2);
    }
    s12[t] = a12; s21[t] = a21; sm[t] = m;
    __syncthreads();
#pragma unroll
    for (int o = FT / 2; o; o >>= 1) {
        if (t < o) {
            s12[t] += s12[t + o];
            s21[t] += s21[t + o];
            sm[t]  += sm[t + o];
        }
        __syncthreads();
    }
    if (t == 0) {
        double D12 = sqrt(s12[0]);
        double D21 = sqrt(s21[0]);
        if (out_size > 0) out[0] = (float)(D12 + D21);   // distance
        if (out_size > 1) out[1] = (float)D12;           // distance1_2
        if (out_size > 2) out[2] = (float)D21;           // distance2_1
        if (out_size > 3) out[3] = (float)sm[0];         // matched_pairs
    }
}

extern "C" void kernel_launch(void* const* d_in, const int* in_sizes, int n_in,
                              void* d_out, int out_size) {
    const float* d1 = (const float*)d_in[0];   // distances1 [4096,4096] f32
    const float* d2 = (const float*)d_in[1];   // distances2 [4096,4096] f32
    float* out = (float*)d_out;

    // Two persistent CTAs, one exact Prim's MST each (runs concurrently).
    mst_kernel<<<2, TPB>>>(d1, d2);
    // Tiny epilogue: gathers + fp64 reductions + matched-pair count.
    finalize_kernel<<<1, 256>>>(d1, d2, out, out_size);
}

// round 5
// speedup vs baseline: 1.1972x; 1.1972x over previous
#include <cuda_runtime.h>
#include <cstdint>
#include <math.h>

// Problem constants
constexpr int NN    = 4096;          // number of vertices / matrix dim
constexpr int TPB   = 1024;          // threads per MST block
constexpr int SLICE = NN / TPB;      // 4 vertices per thread
constexpr int NWARP = TPB / 32;      // 32 warps

// Scratch (no allocations allowed): final Prim parent arrays for both matrices.
__device__ int g_parent[2][NN];

__device__ __forceinline__ unsigned long long u64min(unsigned long long a, unsigned long long b) {
    return b < a ? b : a;
}

// ---------------------------------------------------------------------------
// Exact Prim's MST, one persistent CTA per matrix (gridDim.x == 2).
//
// Thread t owns vertices [4t, 4t+4).
//   md[k] : best edge weight from tree to vertex 4t+k. Sign bit set <=> vertex
//           is in the tree: strict `rv < md` always fails vs negative md, and
//           its u32 bit pattern (>= 0x80000000) loses every unsigned min vs
//           any live (nonnegative-float) candidate.
//   par[k]: tree endpoint realizing md (frozen once the vertex pops).
//
// Argmin matches jnp.argmin (first index) exactly:
//   - thread-local: u64 key (float_bits<<32 | idx), min keeps lowest idx on ties
//   - warp level:   REDUX.MIN on float bits; lane order == vertex order, so the
//                   FIRST lane whose bits equal the min holds the lowest index
//   - cross-warp:   warp id order == vertex-range order; same ballot/ffs trick
// ---------------------------------------------------------------------------
__global__ __launch_bounds__(TPB, 1)
void mst_kernel(const float* __restrict__ d1, const float* __restrict__ d2) {
    const float* __restrict__ D = blockIdx.x ? d2 : d1;
    const int t    = threadIdx.x;
    const int wid  = t >> 5;
    const int lane = t & 31;
    constexpr unsigned FULL = 0xFFFFFFFFu;

    // per-warp winner (bits, idx), double-buffered across iterations
    __shared__ unsigned pb[2][NWARP];
    __shared__ unsigned pi[2][NWARP];

    float md[SLICE];
    int   par[SLICE];

    // ---- init: min_dist = D[0, :], parent = 0, vertex 0 in tree ----
    {
        float4 a = reinterpret_cast<const float4*>(D)[t];
        md[0] = a.x; md[1] = a.y; md[2] = a.z; md[3] = a.w;
    }
#pragma unroll
    for (int k = 0; k < SLICE; ++k) par[k] = 0;
    if (t == 0) md[0] = __uint_as_float(0xFF800000u);   // vertex 0: -inf => in tree

    // thread-local argmin key over owned slice
    unsigned long long key = ~0ull;
#pragma unroll
    for (int k = 0; k < SLICE; ++k) {
        unsigned long long kk =
            ((unsigned long long)__float_as_uint(md[k]) << 32) | (unsigned)(t * SLICE + k);
        key = u64min(key, kk);
    }

    for (int sel = 0; sel < NN - 1; ++sel) {
        const int s = sel & 1;
        const unsigned bits = (unsigned)(key >> 32);
        const unsigned idx  = (unsigned)key;

        // ---- warp phase: single-instruction min + first-matching-lane store ----
        const unsigned wmin = __reduce_min_sync(FULL, bits);
        const unsigned ball = __ballot_sync(FULL, bits == wmin);
        // first lane holding wmin owns the smallest tied vertex index in this warp
        if ((bits == wmin) && ((ball & ((1u << lane) - 1u)) == 0u)) {
            pb[s][wid] = bits;
            pi[s][wid] = idx;
        }
        __syncthreads();

        // ---- cross-warp phase: 32 partials, one per lane ----
        const unsigned b2 = pb[s][lane];
        const unsigned i2 = pi[s][lane];
        const unsigned gmin  = __reduce_min_sync(FULL, b2);
        const unsigned ball2 = __ballot_sync(FULL, b2 == gmin);
        const int src = __ffs((int)ball2) - 1;            // lowest warp id with min
        const int j   = (int)__shfl_sync(FULL, i2, src);  // broadcast winner index

        // owner marks j in-tree (sign-bit flip), static register indexing only
        if ((j >> 2) == t) {
#pragma unroll
            for (int k = 0; k < SLICE; ++k)
                if (k == (j & (SLICE - 1)))
                    md[k] = __uint_as_float(__float_as_uint(md[k]) | 0x80000000u);
        }
        if (sel == NN - 2) break;   // last vertex popped, no relaxation needed

        // ---- relax with row j, fused with local argmin recompute ----
        float4 a = reinterpret_cast<const float4*>(D + (size_t)j * NN)[t];
        float rv[SLICE] = {a.x, a.y, a.z, a.w};
        key = ~0ull;
#pragma unroll
        for (int k = 0; k < SLICE; ++k) {
            if (rv[k] < md[k]) { md[k] = rv[k]; par[k] = j; }   // strict <, matches reference
            unsigned long long kk =
                ((unsigned long long)__float_as_uint(md[k]) << 32) | (unsigned)(t * SLICE + k);
            key = u64min(key, kk);
        }
    }

    // parents are frozen at pop time; write once at the end
#pragma unroll
    for (int k = 0; k < SLICE; ++k)
        g_parent[blockIdx.x][t * SLICE + k] = par[k];
}

// ---------------------------------------------------------------------------
// Gather signatures, fp64 sums, sqrt, matched-pair count.
// Each child c in 1..N-1 appears exactly once in each pair list, so
// matched_pairs = #{ c : parent1[c] == parent2[c] }.
// 1024 threads, 4 children each, fully unrolled -> ~16 outstanding loads/thread.
// ---------------------------------------------------------------------------
__global__ __launch_bounds__(1024)
void finalize_kernel(const float* __restrict__ d1, const float* __restrict__ d2,
                     float* __restrict__ out, int out_size) {
    constexpr int FT = 1024;
    __shared__ double s12[FT];
    __shared__ double s21[FT];
    __shared__ int    sm[FT];
    const int t = threadIdx.x;

    double a12 = 0.0, a21 = 0.0;
    int m = 0;
#pragma unroll
    for (int i = 0; i < 4; ++i) {
        int c = 1 + t + i * FT;
        if (c < NN) {
            int p1 = g_parent[0][c];
            int p2 = g_parent[1][c];
            float x1 = d1[(size_t)p1 * NN + c];   // sig1
            float y1 = d2[(size_t)p1 * NN + c];   // sig1_2
            float x2 = d2[(size_t)p2 * NN + c];   // sig2
            float y2 = d1[(size_t)p2 * NN + c];   // sig2_1
            double e1 = (double)x1 - (double)y1;
            double e2 = (double)x2 - (double)y2;
            a12 += e1 * e1;
            a21 += e2 * e2;
            m += (p1 == p2);
        }
    }
    s12[t] = a12; s21[t] = a21; sm[t] = m;
    __syncthreads();
#pragma unroll
    for (int o = FT / 2; o; o >>= 1) {
        if (t < o) {
            s12[t] += s12[t + o];
            s21[t] += s21[t + o];
            sm[t]  += sm[t + o];
        }
        __syncthreads();
    }
    if (t == 0) {
        double D12 = sqrt(s12[0]);
        double D21 = sqrt(s21[0]);
        if (out_size > 0) out[0] = (float)(D12 + D21);   // distance
        if (out_size > 1) out[1] = (float)D12;           // distance1_2
        if (out_size > 2) out[2] = (float)D21;           // distance2_1
        if (out_size > 3) out[3] = (float)sm[0];         // matched_pairs
    }
}

extern "C" void kernel_launch(void* const* d_in, const int* in_sizes, int n_in,
                              void* d_out, int out_size) {
    const float* d1 = (const float*)d_in[0];   // distances1 [4096,4096] f32
    const float* d2 = (const float*)d_in[1];   // distances2 [4096,4096] f32
    float* out = (float*)d_out;

    // Two persistent CTAs, one exact Prim's MST each (runs concurrently).
    mst_kernel<<<2, TPB>>>(d1, d2);
    // Tiny epilogue: gathers + fp64 reductions + matched-pair count.
    finalize_kernel<<<1, 1024>>>(d1, d2, out, out_size);
}

// round 6
// speedup vs baseline: 1.2956x; 1.0822x over previous
#include <cuda_runtime.h>
#include <cstdint>
#include <math.h>

// Problem constants
constexpr int NN    = 4096;          // number of vertices / matrix dim
constexpr int TPB   = 1024;          // threads per MST block
constexpr int SLICE = NN / TPB;      // 4 vertices per thread
constexpr int NWARP = TPB / 32;      // 32 warps

// Scratch (no allocations allowed): final Prim parent arrays for both matrices.
__device__ int g_parent[2][NN];

__device__ __forceinline__ unsigned long long u64min(unsigned long long a, unsigned long long b) {
    return b < a ? b : a;
}

// ---------------------------------------------------------------------------
// Exact Prim's MST, one persistent CTA per matrix (gridDim.x == 2).
//
// Thread t owns vertices [4t, 4t+4).
//   md[k] : best edge weight from tree to vertex 4t+k. Sign bit set <=> vertex
//           is in the tree: strict `rv < md` always fails vs negative md, and
//           its u32 bit pattern (>= 0x80000000) loses every unsigned min vs
//           any live (nonnegative-float) candidate.
//   par[k]: tree endpoint realizing md (frozen once the vertex pops).
//
// Argmin matches jnp.argmin (first index) exactly:
//   - thread-local: u64 key (float_bits<<32 | idx), min keeps lowest idx on ties
//   - warp level:   REDUX.MIN on float bits; lane order == vertex order, so the
//                   FIRST lane whose bits equal the min holds the lowest index
//   - cross-warp:   warp id order == vertex-range order; same ballot/ffs trick
//
// Latency hiding: rows are read exactly once each (no reuse), so after issuing
// the row-j load we compute the global runner-up j2 (next winner unless the
// fresh relaxation wins) and prefetch row j2 into L2. Pure cache hint — the
// pop sequence is unaffected.
// ---------------------------------------------------------------------------
__global__ __launch_bounds__(TPB, 1)
void mst_kernel(const float* __restrict__ d1, const float* __restrict__ d2) {
    const float* __restrict__ D = blockIdx.x ? d2 : d1;
    const int t    = threadIdx.x;
    const int wid  = t >> 5;
    const int lane = t & 31;
    constexpr unsigned FULL = 0xFFFFFFFFu;

    // per-warp winner (bits, idx), double-buffered across iterations
    __shared__ unsigned pb[2][NWARP];
    __shared__ unsigned pi[2][NWARP];

    float md[SLICE];
    int   par[SLICE];

    // ---- init: min_dist = D[0, :], parent = 0, vertex 0 in tree ----
    {
        float4 a = reinterpret_cast<const float4*>(D)[t];
        md[0] = a.x; md[1] = a.y; md[2] = a.z; md[3] = a.w;
    }
#pragma unroll
    for (int k = 0; k < SLICE; ++k) par[k] = 0;
    if (t == 0) md[0] = __uint_as_float(0xFF800000u);   // vertex 0: -inf => in tree

    // thread-local argmin key over owned slice
    unsigned long long key = ~0ull;
#pragma unroll
    for (int k = 0; k < SLICE; ++k) {
        unsigned long long kk =
            ((unsigned long long)__float_as_uint(md[k]) << 32) | (unsigned)(t * SLICE + k);
        key = u64min(key, kk);
    }

    for (int sel = 0; sel < NN - 1; ++sel) {
        const int s = sel & 1;
        const unsigned bits = (unsigned)(key >> 32);
        const unsigned idx  = (unsigned)key;

        // ---- warp phase: single-instruction min + first-matching-lane store ----
        const unsigned wmin = __reduce_min_sync(FULL, bits);
        const unsigned ball = __ballot_sync(FULL, bits == wmin);
        // first lane holding wmin owns the smallest tied vertex index in this warp
        if ((bits == wmin) && ((ball & ((1u << lane) - 1u)) == 0u)) {
            pb[s][wid] = bits;
            pi[s][wid] = idx;
        }
        __syncthreads();

        // ---- cross-warp phase: 32 partials, one per lane ----
        const unsigned b2 = pb[s][lane];
        const unsigned i2 = pi[s][lane];
        const unsigned gmin  = __reduce_min_sync(FULL, b2);
        const unsigned ball2 = __ballot_sync(FULL, b2 == gmin);
        const int src = __ffs((int)ball2) - 1;            // lowest warp id with min
        const int j   = (int)__shfl_sync(FULL, i2, src);  // broadcast winner index

        // owner marks j in-tree (sign-bit flip), static register indexing only
        if ((j >> 2) == t) {
#pragma unroll
            for (int k = 0; k < SLICE; ++k)
                if (k == (j & (SLICE - 1)))
                    md[k] = __uint_as_float(__float_as_uint(md[k]) | 0x80000000u);
        }
        if (sel == NN - 2) break;   // last vertex popped, no relaxation needed

        // ---- issue the row-j load FIRST (critical path) ----
        float4 a = reinterpret_cast<const float4*>(D + (size_t)j * NN)[t];

        // ---- runner-up j2 from the same partials; prefetch its row to L2.
        //      This chain hides entirely under the row-j load latency. ----
        {
            const unsigned b2x   = (lane == src) ? 0xFFFFFFFFu : b2;
            const unsigned gmin2 = __reduce_min_sync(FULL, b2x);
            const unsigned ball3 = __ballot_sync(FULL, b2x == gmin2);
            const int src2 = __ffs((int)ball3) - 1;
            const int j2   = (int)__shfl_sync(FULL, i2, src2);
            if (t < NN / 32) {   // 128 threads, one 128B line each -> full 16KB row
                const char* p = reinterpret_cast<const char*>(D + (size_t)j2 * NN) + t * 128;
                asm volatile("prefetch.global.L2 [%0];" :: "l"(p));
            }
        }

        // ---- relax with row j, fused with local argmin recompute ----
        float rv[SLICE] = {a.x, a.y, a.z, a.w};
        key = ~0ull;
#pragma unroll
        for (int k = 0; k < SLICE; ++k) {
            if (rv[k] < md[k]) { md[k] = rv[k]; par[k] = j; }   // strict <, matches reference
            unsigned long long kk =
                ((unsigned long long)__float_as_uint(md[k]) << 32) | (unsigned)(t * SLICE + k);
            key = u64min(key, kk);
        }
    }

    // parents are frozen at pop time; write once at the end
#pragma unroll
    for (int k = 0; k < SLICE; ++k)
        g_parent[blockIdx.x][t * SLICE + k] = par[k];
}

// ---------------------------------------------------------------------------
// Gather signatures, fp64 sums, sqrt, matched-pair count.
// Each child c in 1..N-1 appears exactly once in each pair list, so
// matched_pairs = #{ c : parent1[c] == parent2[c] }.
// ---------------------------------------------------------------------------
__global__ __launch_bounds__(1024)
void finalize_kernel(const float* __restrict__ d1, const float* __restrict__ d2,
                     float* __restrict__ out, int out_size) {
    constexpr int FT = 1024;
    __shared__ double s12[FT];
    __shared__ double s21[FT];
    __shared__ int    sm[FT];
    const int t = threadIdx.x;

    double a12 = 0.0, a21 = 0.0;
    int m = 0;
#pragma unroll
    for (int i = 0; i < 4; ++i) {
        int c = 1 + t + i * FT;
        if (c < NN) {
            int p1 = g_parent[0][c];
            int p2 = g_parent[1][c];
            float x1 = d1[(size_t)p1 * NN + c];   // sig1
            float y1 = d2[(size_t)p1 * NN + c];   // sig1_2
            float x2 = d2[(size_t)p2 * NN + c];   // sig2
            float y2 = d1[(size_t)p2 * NN + c];   // sig2_1
            double e1 = (double)x1 - (double)y1;
            double e2 = (double)x2 - (double)y2;
            a12 += e1 * e1;
            a21 += e2 * e2;
            m += (p1 == p2);
        }
    }
    s12[t] = a12; s21[t] = a21; sm[t] = m;
    __syncthreads();
#pragma unroll
    for (int o = FT / 2; o; o >>= 1) {
        if (t < o) {
            s12[t] += s12[t + o];
            s21[t] += s21[t + o];
            sm[t]  += sm[t + o];
        }
        __syncthreads();
    }
    if (t == 0) {
        double D12 = sqrt(s12[0]);
        double D21 = sqrt(s21[0]);
        if (out_size > 0) out[0] = (float)(D12 + D21);   // distance
        if (out_size > 1) out[1] = (float)D12;           // distance1_2
        if (out_size > 2) out[2] = (float)D21;           // distance2_1
        if (out_size > 3) out[3] = (float)sm[0];         // matched_pairs
    }
}

extern "C" void kernel_launch(void* const* d_in, const int* in_sizes, int n_in,
                              void* d_out, int out_size) {
    const float* d1 = (const float*)d_in[0];   // distances1 [4096,4096] f32
    const float* d2 = (const float*)d_in[1];   // distances2 [4096,4096] f32
    float* out = (float*)d_out;

    // Two persistent CTAs, one exact Prim's MST each (runs concurrently).
    mst_kernel<<<2, TPB>>>(d1, d2);
    // Tiny epilogue: gathers + fp64 reductions + matched-pair count.
    finalize_kernel<<<1, 1024>>>(d1, d2, out, out_size);
}